// round 5
// baseline (speedup 1.0000x reference)
#include <cuda_runtime.h>
#include <cstdint>

// ---------------------------------------------------------------------------
// DecayTGNMemoryModule — fused FP32 (f32x2-packed) implementation
//   pm  = relu(msg @ W1^T + b1) @ W2^T + b2
//   h   = memory[id] * exp(-0.1 * max(ts - last_update[id], 0))
//   GRU: r,z = sig(gx+gh), n = tanh(gx_n + r*gh_n), h' = (1-z)n + z h
//   out = memory, with out[id] = h'[last event for id]
// ---------------------------------------------------------------------------

constexpr int NODES = 200000;
constexpr int H     = 128;
constexpr int MSG   = 172;
constexpr int BT    = 32;          // events per block
constexpr int SMEM_BYTES = (BT * MSG + 3 * BT * H) * 4;   // 71168 B

// k-major packed weights: Wp[kq][row] holds float4 = W[row][4kq..4kq+3]
__device__ float4 g_W1p [43 * 128];   // K=172 -> 43 kq, 128 rows
__device__ float4 g_W2p [32 * 128];   // K=128 -> 32 kq, 128 rows
__device__ float4 g_Wihp[32 * 384];   // K=128, 384 rows
__device__ float4 g_Whhp[32 * 384];
__device__ int    g_last_pos[NODES];

// packed f32x2 fma: acc += a * b (elementwise on the pair)
__device__ __forceinline__ void ffma2(unsigned long long& acc,
                                      unsigned long long a,
                                      unsigned long long b) {
    asm("fma.rn.f32x2 %0, %1, %2, %0;" : "+l"(acc) : "l"(a), "l"(b));
}

__device__ __forceinline__ float fsum2(unsigned long long v) {
    float lo, hi;
    asm("mov.b64 {%0, %1}, %2;" : "=f"(lo), "=f"(hi) : "l"(v));
    return lo + hi;
}

__device__ __forceinline__ float sigmoidf_(float x) {
    return 1.0f / (1.0f + __expf(-x));
}

// Accumulate acc[i] (i indexes 16 events) += sum_k W[row j][k] * src[e][k]
// Wp: packed k-major, WSTRIDE rows per kq. src: smem, row stride K = 4*KQ.
// All activation LDS addresses are warp-uniform -> broadcast (N=1).
template <int KQ, int WSTRIDE>
__device__ __forceinline__ void accum16(unsigned long long acc[16],
                                        const float4* __restrict__ Wp, int j,
                                        const float* src, int e0) {
    constexpr int K = KQ * 4;
    const float* sbase = src + e0 * K;
    #pragma unroll 2
    for (int kq = 0; kq < KQ; ++kq) {
        ulonglong2 w = *reinterpret_cast<const ulonglong2*>(Wp + kq * WSTRIDE + j);
        #pragma unroll
        for (int i = 0; i < 16; ++i) {
            ulonglong2 x = *reinterpret_cast<const ulonglong2*>(sbase + i * K + 4 * kq);
            ffma2(acc[i], w.x, x.x);
            ffma2(acc[i], w.y, x.y);
        }
    }
}

// ---------------------------------------------------------------------------
// Kernel 1: copy memory->out, reset last_pos, repack weights k-major
// ---------------------------------------------------------------------------
__global__ void k_prep(const float* __restrict__ memory,
                       const float* __restrict__ W1,
                       const float* __restrict__ W2,
                       const float* __restrict__ Wih,
                       const float* __restrict__ Whh,
                       float* __restrict__ out) {
    int tid = blockIdx.x * blockDim.x + threadIdx.x;
    int stride = gridDim.x * blockDim.x;

    const float4* m4 = reinterpret_cast<const float4*>(memory);
    float4* o4 = reinterpret_cast<float4*>(out);
    for (int i = tid; i < NODES * H / 4; i += stride) o4[i] = m4[i];

    for (int i = tid; i < NODES; i += stride) g_last_pos[i] = -1;

    for (int i = tid; i < 43 * 128; i += stride) {
        int kq = i >> 7, d = i & 127;
        const float* p = W1 + d * MSG + 4 * kq;
        g_W1p[i] = make_float4(p[0], p[1], p[2], p[3]);
    }
    for (int i = tid; i < 32 * 128; i += stride) {
        int kq = i >> 7, d = i & 127;
        const float* p = W2 + d * H + 4 * kq;
        g_W2p[i] = make_float4(p[0], p[1], p[2], p[3]);
    }
    for (int i = tid; i < 32 * 384; i += stride) {
        int kq = i / 384, j = i % 384;
        const float* p = Wih + j * H + 4 * kq;
        g_Wihp[i] = make_float4(p[0], p[1], p[2], p[3]);
        const float* q = Whh + j * H + 4 * kq;
        g_Whhp[i] = make_float4(q[0], q[1], q[2], q[3]);
    }
}

// ---------------------------------------------------------------------------
// Kernel 2: last event wins
// ---------------------------------------------------------------------------
__global__ void k_scatter(const int* __restrict__ ids, int n) {
    int gi = blockIdx.x * blockDim.x + threadIdx.x;
    if (gi < n) {
        int id = ids[gi];
        id = id < 0 ? 0 : (id >= NODES ? NODES - 1 : id);
        atomicMax(&g_last_pos[id], gi);
    }
}

// ---------------------------------------------------------------------------
// Kernel 3: fused MLP + decay gather + GRU + scatter
// 256 threads, BT=32 events. thread = (dim d in [0,128), event-half e0).
// ---------------------------------------------------------------------------
__global__ void __launch_bounds__(256) k_update(
    const int* __restrict__ ids, const float* __restrict__ msgs,
    const float* __restrict__ ts, const float* __restrict__ memory,
    const float* __restrict__ lu,
    const float* __restrict__ b1, const float* __restrict__ b2,
    const float* __restrict__ bih, const float* __restrict__ bhh,
    float* __restrict__ out, int n) {
    extern __shared__ float sm[];
    float* msg_s = sm;                    // [BT][MSG]
    float* t1_s  = sm + BT * MSG;         // [BT][H]
    float* pm_s  = t1_s + BT * H;         // [BT][H]
    float* h_s   = pm_s + BT * H;         // [BT][H]
    __shared__ int id_s[BT];
    __shared__ int win_s[BT];

    int tid = threadIdx.x, warp = tid >> 5, lane = tid & 31;
    int base = blockIdx.x * BT;

    // ---- pass 0: gather decayed memory + stage messages (warp per event) ----
    for (int e = warp; e < BT; e += 8) {
        int gi = base + e;
        if (gi < n) {
            int id = ids[gi];
            id = id < 0 ? 0 : (id >= NODES ? NODES - 1 : id);
            float dt = fmaxf(ts[gi] - lu[id], 0.0f);
            float sc = __expf(-0.1f * dt);
            float4 m = reinterpret_cast<const float4*>(memory)[(size_t)id * (H / 4) + lane];
            reinterpret_cast<float4*>(h_s + e * H)[lane] =
                make_float4(m.x * sc, m.y * sc, m.z * sc, m.w * sc);
            const float4* gr = reinterpret_cast<const float4*>(msgs) + (size_t)gi * (MSG / 4);
            float4* sr = reinterpret_cast<float4*>(msg_s + e * MSG);
            for (int j = lane; j < MSG / 4; j += 32) sr[j] = gr[j];
            if (lane == 0) { id_s[e] = id; win_s[e] = (g_last_pos[id] == gi); }
        } else {
            reinterpret_cast<float4*>(h_s + e * H)[lane] = make_float4(0, 0, 0, 0);
            for (int j = lane; j < MSG / 4; j += 32)
                reinterpret_cast<float4*>(msg_s + e * MSG)[j] = make_float4(0, 0, 0, 0);
            if (lane == 0) { id_s[e] = 0; win_s[e] = 0; }
        }
    }
    __syncthreads();

    int d  = tid & 127;
    int e0 = (tid >> 7) << 4;   // 0 or 16

    unsigned long long acc[16];

    // ---- pass 1: t1 = relu(msg @ W1^T + b1) ----
    #pragma unroll
    for (int i = 0; i < 16; ++i) acc[i] = 0ull;
    accum16<43, 128>(acc, g_W1p, d, msg_s, e0);
    {
        float bb = b1[d];
        #pragma unroll
        for (int i = 0; i < 16; ++i)
            t1_s[(e0 + i) * H + d] = fmaxf(fsum2(acc[i]) + bb, 0.0f);
    }
    __syncthreads();

    // ---- pass 2: pm = t1 @ W2^T + b2 ----
    #pragma unroll
    for (int i = 0; i < 16; ++i) acc[i] = 0ull;
    accum16<32, 128>(acc, g_W2p, d, t1_s, e0);
    {
        float bb = b2[d];
        #pragma unroll
        for (int i = 0; i < 16; ++i)
            pm_s[(e0 + i) * H + d] = fsum2(acc[i]) + bb;
    }
    __syncthreads();

    float r_[16], z_[16], gxn_[16];

    // ---- pass 3: r = sigmoid(gx_r + gh_r) ----
    #pragma unroll
    for (int i = 0; i < 16; ++i) acc[i] = 0ull;
    accum16<32, 384>(acc, g_Wihp, d, pm_s, e0);
    accum16<32, 384>(acc, g_Whhp, d, h_s, e0);
    {
        float bb = bih[d] + bhh[d];
        #pragma unroll
        for (int i = 0; i < 16; ++i) r_[i] = sigmoidf_(fsum2(acc[i]) + bb);
    }

    // ---- pass 4: z = sigmoid(gx_z + gh_z) ----
    #pragma unroll
    for (int i = 0; i < 16; ++i) acc[i] = 0ull;
    accum16<32, 384>(acc, g_Wihp, d + 128, pm_s, e0);
    accum16<32, 384>(acc, g_Whhp, d + 128, h_s, e0);
    {
        float bb = bih[d + 128] + bhh[d + 128];
        #pragma unroll
        for (int i = 0; i < 16; ++i) z_[i] = sigmoidf_(fsum2(acc[i]) + bb);
    }

    // ---- pass 5a: gx_n ----
    #pragma unroll
    for (int i = 0; i < 16; ++i) acc[i] = 0ull;
    accum16<32, 384>(acc, g_Wihp, d + 256, pm_s, e0);
    {
        float bb = bih[d + 256];
        #pragma unroll
        for (int i = 0; i < 16; ++i) gxn_[i] = fsum2(acc[i]) + bb;
    }

    // ---- pass 5b: gh_n, then gate combine + scatter ----
    #pragma unroll
    for (int i = 0; i < 16; ++i) acc[i] = 0ull;
    accum16<32, 384>(acc, g_Whhp, d + 256, h_s, e0);
    {
        float bbn = bhh[d + 256];
        #pragma unroll
        for (int i = 0; i < 16; ++i) {
            int e = e0 + i;
            float ghn = fsum2(acc[i]) + bbn;
            float nn = tanhf(fmaf(r_[i], ghn, gxn_[i]));
            float hv = h_s[e * H + d];
            float hn = fmaf(z_[i], hv - nn, nn);   // (1-z)n + z h
            if (win_s[e]) out[(size_t)id_s[e] * H + d] = hn;
        }
    }
}

// ---------------------------------------------------------------------------
// kernel_launch
// inputs: 0 node_ids, 1 messages, 2 timestamps, 3 memory, 4 last_update,
//         5 W1, 6 b1, 7 W2, 8 b2, 9 W_ih, 10 W_hh, 11 b_ih, 12 b_hh
// ---------------------------------------------------------------------------
extern "C" void kernel_launch(void* const* d_in, const int* in_sizes, int n_in,
                              void* d_out, int out_size) {
    const int*   ids    = (const int*)  d_in[0];
    const float* msgs   = (const float*)d_in[1];
    const float* ts     = (const float*)d_in[2];
    const float* memory = (const float*)d_in[3];
    const float* lu     = (const float*)d_in[4];
    const float* W1     = (const float*)d_in[5];
    const float* b1     = (const float*)d_in[6];
    const float* W2     = (const float*)d_in[7];
    const float* b2     = (const float*)d_in[8];
    const float* Wih    = (const float*)d_in[9];
    const float* Whh    = (const float*)d_in[10];
    const float* bih    = (const float*)d_in[11];
    const float* bhh    = (const float*)d_in[12];
    float* out = (float*)d_out;

    int n = in_sizes[0];

    cudaFuncSetAttribute(k_update, cudaFuncAttributeMaxDynamicSharedMemorySize,
                         SMEM_BYTES);

    k_prep<<<2048, 256>>>(memory, W1, W2, Wih, Whh, out);
    k_scatter<<<(n + 255) / 256, 256>>>(ids, n);
    k_update<<<(n + BT - 1) / BT, 256, SMEM_BYTES>>>(
        ids, msgs, ts, memory, lu, b1, b2, bih, bhh, out, n);
}